// round 12
// baseline (speedup 1.0000x reference)
#include <cuda_runtime.h>

#define Nb 32
#define Qn 300
#define Cc 92
#define Tt 32
#define NTHR 512
#define NWARP (NTHR/32)
#define INF 1e30f
#define CSTRIDE 301   // padded smem row stride
#define KMAX 10       // ceil(300/32) columns per lane (warp-0 solver)
#define LSH_BYTES (Qn * Cc * 4)   // 110,400 B dynamic smem for logits

__device__ float    g_bsum[Nb];
__device__ unsigned g_done = 0;

// order-preserving float<->uint keys for min-reductions
__device__ __forceinline__ unsigned okey(float f) {
    unsigned bb = __float_as_uint(f);
    return bb ^ (unsigned)(((int)bb >> 31) | 0x80000000);
}
__device__ __forceinline__ float unkey(unsigned k) {
    unsigned bb = (k & 0x80000000u) ? (k ^ 0x80000000u) : ~k;
    return __uint_as_float(bb);
}

__device__ __forceinline__ unsigned smem_u32(const void* p) {
    unsigned a;
    asm("{ .reg .u64 t; cvta.to.shared.u64 t, %1; cvt.u32.u64 %0, t; }"
        : "=r"(a) : "l"(p));
    return a;
}

struct TgtGeom {            // precomputed per-target geometry
    float tx, ty, tw, th;   // raw cxcywh
    float bx0, by0, bx1, by1, areaB;
    int   lab;
};

__device__ __forceinline__ float pair_cost_fast(
    float cx, float cy, float w, float h,
    float ax0, float ay0, float ax1, float ay1, float areaA,
    float lv, float inv_s, const TgtGeom& T)
{
    float pc = __expf(lv) * inv_s;   // no max-shift: logits are O(1), fp32 safe
    float cbbox = fabsf(cx - T.tx) + fabsf(cy - T.ty) + fabsf(w - T.tw) + fabsf(h - T.th);
    float iw = fminf(ax1, T.bx1) - fmaxf(ax0, T.bx0); iw = fmaxf(iw, 0.f);
    float ih = fminf(ay1, T.by1) - fmaxf(ay0, T.by0); ih = fmaxf(ih, 0.f);
    float inter = iw * ih;
    float uni = areaA + T.areaB - inter;
    float iou = __fdividef(inter, uni);
    float cw = fmaxf(ax1, T.bx1) - fminf(ax0, T.bx0);
    float ch = fmaxf(ay1, T.by1) - fminf(ay0, T.by0);
    float areaC = cw * ch;
    float giou = iou - __fdividef(areaC - uni, areaC);
    return 5.f * cbbox - pc - 2.f * giou;
}

// ---------------------------------------------------------------------------
// Single fused kernel: one block per batch; last block reduces to out[0].
//  A)  TMA logits -> smem (single shot), overlapped with:
//  B1) warp-per-query softmax denominators FROM GMEM (coalesced, 16 warps)
//  B2) flat pair cost fill + per-row argmin via 64-bit smem atomicMin (C fused)
//  D)  collision resolution  E) JV augmentation (warp 0)
//  F)  matched sum vs GLOBAL targets 0..31; parallel last-block reduce
// ---------------------------------------------------------------------------
__global__ __launch_bounds__(NTHR, 1)
void fused_kernel(const float* __restrict__ logits,
                  const float* __restrict__ boxes,
                  const int*   __restrict__ lab32,
                  const float* __restrict__ tboxes,
                  float* __restrict__ out) {
    extern __shared__ float lsh[];    // [Qn*Cc] logits for this batch
    __shared__ float csh[Tt * CSTRIDE];
    __shared__ TgtGeom tloc[Tt];      // batch b's own targets (LSA block)
    __shared__ TgtGeom tg0[Tt];       // GLOBAL targets 0..31 (final sum)
    __shared__ float qinv[Qn];
    __shared__ float4 qbox[Qn];
    __shared__ unsigned long long rmin[Tt];   // fused row-argmin (key<<32 | q)
    __shared__ float u_sh[Tt + 1];
    __shared__ int   p_sh[Qn + 1];
    __shared__ float wred[NWARP];
    __shared__ int   s_flag;
    __shared__ __align__(8) unsigned long long mbar;

    const int b = blockIdx.x;
    const int tid = threadIdx.x;
    const int lane = tid & 31;
    const int wid = tid >> 5;
    const unsigned FULL = 0xffffffffu;

    // ---- A0: init mbarrier + kick off TMA bulk copy of logits ----
    const unsigned mbar_a = smem_u32(&mbar);
    if (tid == 0) {
        asm volatile("mbarrier.init.shared.b64 [%0], 1;" :: "r"(mbar_a) : "memory");
        asm volatile("fence.proxy.async.shared::cta;" ::: "memory");
        const unsigned dst = smem_u32(lsh);
        const float* src = logits + (size_t)b * Qn * Cc;
        asm volatile("mbarrier.arrive.expect_tx.shared.b64 _, [%0], %1;"
                     :: "r"(mbar_a), "r"((unsigned)LSH_BYTES) : "memory");
        asm volatile("cp.async.bulk.shared::cta.global.mbarrier::complete_tx::bytes "
                     "[%0], [%1], %2, [%3];"
                     :: "r"(dst), "l"(src), "r"((unsigned)LSH_BYTES), "r"(mbar_a)
                     : "memory");
        s_flag = 0;
    }

    // ---- A1 (overlapped): init, label detect, boxes, geometry, rmin ----
    for (int k = tid; k <= Qn; k += NTHR) p_sh[k] = 0;
    for (int q = tid; q < Qn; q += NTHR)
        qbox[q] = *(const float4*)(boxes + ((size_t)b * Qn + q) * 4);
    if (tid < Tt) rmin[tid] = 0xFFFFFFFFFFFFFFFFull;
    int any = 0;
    for (int k = 1 + 2 * tid; k < Nb * Tt; k += 2 * NTHR)
        if (lab32[k] != 0) any = 1;
    if (__syncthreads_or(any)) { if (tid == 0) s_flag = 1; }
    __syncthreads();   // publishes s_flag, rmin init, mbar init
    const int is64 = (s_flag == 0);

    if (tid < 2 * Tt) {
        int t = tid & (Tt - 1);
        int gt = (tid < Tt) ? (b * Tt + t) : t;
        TgtGeom T;
        const float* tb = tboxes + (size_t)gt * 4;
        T.tx = tb[0]; T.ty = tb[1]; T.tw = tb[2]; T.th = tb[3];
        T.bx0 = T.tx - 0.5f * T.tw; T.by0 = T.ty - 0.5f * T.th;
        T.bx1 = T.tx + 0.5f * T.tw; T.by1 = T.ty + 0.5f * T.th;
        T.areaB = (T.bx1 - T.bx0) * (T.by1 - T.by0);
        T.lab = is64 ? lab32[2 * gt] : lab32[gt];
        if (tid < Tt) tloc[t] = T; else tg0[t] = T;
    }

    // ---- B1 (overlapped with TMA): warp-per-query denominators from GMEM ----
    for (int q = wid; q < Qn; q += NWARP) {
        const float* l = logits + ((size_t)b * Qn + q) * Cc;
        float s = 0.f;
        #pragma unroll
        for (int c = lane; c < Cc; c += 32) s += __expf(l[c]);
        #pragma unroll
        for (int off = 16; off > 0; off >>= 1)
            s += __shfl_xor_sync(FULL, s, off);
        if (lane == 0) qinv[q] = __fdividef(1.f, s);
    }
    __syncthreads();   // qinv + geometry visible

    // ---- wait for TMA completion (likely already done), then B2 ----
    asm volatile(
        "{\n\t.reg .pred P;\n\t"
        "W0:\n\t"
        "mbarrier.try_wait.parity.shared.b64 P, [%0], 0;\n\t"
        "@!P bra W0;\n\t}"
        :: "r"(mbar_a) : "memory");

    // ---- B2: pair costs + fused per-row argmin (register min, 1 atomic) ----
    {
        const int t = tid & 31;
        const TgtGeom T = tloc[t];
        unsigned long long myMin = 0xFFFFFFFFFFFFFFFFull;
        for (int q = tid >> 5; q < Qn; q += NTHR / 32) {
            float4 bx = qbox[q];
            float cx = bx.x, cy = bx.y, w = bx.z, h = bx.w;
            float ax0 = cx - 0.5f * w, ay0 = cy - 0.5f * h;
            float ax1 = cx + 0.5f * w, ay1 = cy + 0.5f * h;
            float areaA = (ax1 - ax0) * (ay1 - ay0);
            float lv = lsh[q * Cc + T.lab];
            float c = pair_cost_fast(cx, cy, w, h, ax0, ay0, ax1, ay1, areaA,
                                     lv, qinv[q], T);
            csh[t * CSTRIDE + q] = c;
            unsigned long long key = ((unsigned long long)okey(c) << 32) | (unsigned)q;
            myMin = (key < myMin) ? key : myMin;
        }
        atomicMin(&rmin[t], myMin);
    }
    __syncthreads();

    // ---- D + E: warp 0 resolves collisions, augments leftovers ----
    if (wid == 0) {
        unsigned long long rm = rmin[lane];
        u_sh[lane + 1] = unkey((unsigned)(rm >> 32));
        int candv = (int)(rm & 0xFFFFFFFFu) + 1;
        __syncwarp();
        unsigned grp = __match_any_sync(FULL, candv);
        int leader = __ffs(grp) - 1;
        if (lane == leader) p_sh[candv] = lane + 1;
        unsigned un = __ballot_sync(FULL, lane != leader);
        __syncwarp();

        float v[KMAX], minv[KMAX], dacc[KMAX], uofp[KMAX];
        int   way[KMAX], prow[KMAX];
        #pragma unroll
        for (int k = 0; k < KMAX; k++) v[k] = 0.f;

        while (un) {
            int trow = __ffs(un) - 1; un &= un - 1;
            const int i = trow + 1;

            if (lane == 0) p_sh[0] = i;   // anchor for augmenting walk
            unsigned umask = 0;
            float dsum = 0.f;
            #pragma unroll
            for (int k = 0; k < KMAX; k++) {
                int q = 32 * k + lane;
                if (q < Qn) {
                    minv[k] = INF; dacc[k] = 0.f; way[k] = 0;
                    int r = p_sh[q + 1];
                    prow[k] = r;
                    uofp[k] = (r > 0) ? u_sh[r] : 0.f;
                }
            }
            __syncwarp();

            int j0 = 0, i0 = i;
            float u_i0 = u_sh[i];

            while (true) {
                if (j0 > 0 && ((j0 - 1) & 31) == lane)
                    umask |= 1u << ((j0 - 1) >> 5);

                float lmin = INF, luofp = 0.f;
                int lcol = 0, lprow = 0;
                const float* crow = &csh[(i0 - 1) * CSTRIDE];
                #pragma unroll
                for (int k = 0; k < KMAX; k++) {
                    int q = 32 * k + lane;
                    if (q < Qn && !((umask >> k) & 1u)) {
                        float cur = crow[q] - u_i0 - v[k];
                        if (cur < minv[k]) { minv[k] = cur; way[k] = j0; }
                        if (minv[k] < lmin) {
                            lmin = minv[k]; lcol = q + 1;
                            lprow = prow[k]; luofp = uofp[k];
                        }
                    }
                }

                unsigned key = okey(lmin);
                unsigned kmin = __reduce_min_sync(FULL, key);
                float delta = unkey(kmin);
                unsigned bal = __ballot_sync(FULL, key == kmin);
                int src = __ffs(bal) - 1;
                int   j1  = __shfl_sync(FULL, lcol, src);
                int   pj1 = __shfl_sync(FULL, lprow, src);
                float unx = __shfl_sync(FULL, luofp, src);

                dsum += delta;
                #pragma unroll
                for (int k = 0; k < KMAX; k++) {
                    int q = 32 * k + lane;
                    if (q < Qn) {
                        if ((umask >> k) & 1u) { v[k] -= delta; dacc[k] += delta; }
                        else                    minv[k] -= delta;
                    }
                }

                j0 = j1; i0 = pj1; u_i0 = unx;
                if (pj1 == 0) break;
            }

            #pragma unroll
            for (int k = 0; k < KMAX; k++) {
                int q = 32 * k + lane;
                if (q < Qn && ((umask >> k) & 1u) && prow[k] > 0)
                    u_sh[prow[k]] += dacc[k];
            }
            if (lane == 0) u_sh[i] += dsum;
            __syncwarp();

            int cur = j0;
            while (cur) {
                int candw = 0;
                #pragma unroll
                for (int k = 0; k < KMAX; k++)
                    if (32 * k + lane + 1 == cur) candw = way[k];
                int owner = (cur - 1) & 31;
                int wj = __shfl_sync(FULL, candw, owner);
                if (lane == 0) p_sh[cur] = p_sh[wj];
                cur = wj;
            }
            __syncwarp();
        }
    }
    __syncthreads();

    // ---- F: matched sum vs GLOBAL targets 0..31 ----
    float acc = 0.f;
    for (int j = tid + 1; j <= Qn; j += NTHR) {
        int r = p_sh[j];
        if (r > 0) {
            int q = j - 1;
            float4 bx = qbox[q];
            float cx = bx.x, cy = bx.y, w = bx.z, h = bx.w;
            float ax0 = cx - 0.5f * w, ay0 = cy - 0.5f * h;
            float ax1 = cx + 0.5f * w, ay1 = cy + 0.5f * h;
            float areaA = (ax1 - ax0) * (ay1 - ay0);
            const TgtGeom T = tg0[r - 1];
            float lv = lsh[q * Cc + T.lab];
            acc += pair_cost_fast(cx, cy, w, h, ax0, ay0, ax1, ay1, areaA,
                                  lv, qinv[q], T);
        }
    }
    #pragma unroll
    for (int off = 16; off > 0; off >>= 1)
        acc += __shfl_xor_sync(FULL, acc, off);
    if (lane == 0) wred[wid] = acc;
    __syncthreads();

    // ---- tail: block sum, then parallel last-block reduce (warp 0) ----
    if (wid == 0) {
        int isLast = 0;
        if (lane == 0) {
            float tot = 0.f;
            #pragma unroll
            for (int k = 0; k < NWARP; k++) tot += wred[k];
            g_bsum[b] = tot;
            __threadfence();
            isLast = (atomicAdd(&g_done, 1u) == Nb - 1);
        }
        isLast = __shfl_sync(FULL, isLast, 0);
        if (isLast) {
            __threadfence();                       // acquire all g_bsum writes
            float s = g_bsum[lane];                // 32 concurrent loads
            #pragma unroll
            for (int off = 16; off > 0; off >>= 1)
                s += __shfl_xor_sync(FULL, s, off);  // fixed-order tree: deterministic
            if (lane == 0) {
                out[0] = s;
                atomicExch(&g_done, 0u);           // reset for next replay
            }
        }
    }
}

extern "C" void kernel_launch(void* const* d_in, const int* in_sizes, int n_in,
                              void* d_out, int out_size) {
    const float* pred_logits = (const float*)d_in[0];
    const float* pred_boxes  = (const float*)d_in[1];
    const int*   tgt_lab32   = (const int*)d_in[2];   // int32 view; layout auto-detected
    const float* tgt_boxes   = (const float*)d_in[3];
    float* out = (float*)d_out;

    cudaFuncSetAttribute(fused_kernel,
                         cudaFuncAttributeMaxDynamicSharedMemorySize, LSH_BYTES);
    fused_kernel<<<Nb, NTHR, LSH_BYTES>>>(pred_logits, pred_boxes, tgt_lab32,
                                          tgt_boxes, out);
}

// round 13
// speedup vs baseline: 1.2092x; 1.2092x over previous
#include <cuda_runtime.h>

#define Nb 32
#define Qn 300
#define Cc 92
#define Tt 32
#define NTHR 512
#define NWARP (NTHR/32)
#define INF 1e30f
#define CSTRIDE 301   // padded smem row stride
#define KMAX 10       // ceil(300/32) columns per lane (warp-0 solver)
#define LSH_BYTES (Qn * Cc * 4)   // 110,400 B dynamic smem for logits

__device__ float    g_bsum[Nb];
__device__ unsigned g_done = 0;

// order-preserving float<->uint keys for min-reductions
__device__ __forceinline__ unsigned okey(float f) {
    unsigned bb = __float_as_uint(f);
    return bb ^ (unsigned)(((int)bb >> 31) | 0x80000000);
}
__device__ __forceinline__ float unkey(unsigned k) {
    unsigned bb = (k & 0x80000000u) ? (k ^ 0x80000000u) : ~k;
    return __uint_as_float(bb);
}

__device__ __forceinline__ unsigned smem_u32(const void* p) {
    unsigned a;
    asm("{ .reg .u64 t; cvta.to.shared.u64 t, %1; cvt.u32.u64 %0, t; }"
        : "=r"(a) : "l"(p));
    return a;
}

struct TgtGeom {            // precomputed per-target geometry
    float tx, ty, tw, th;   // raw cxcywh
    float bx0, by0, bx1, by1, areaB;
    int   lab;
};

__device__ __forceinline__ float pair_cost_fast(
    float cx, float cy, float w, float h,
    float ax0, float ay0, float ax1, float ay1, float areaA,
    float lv, float inv_s, const TgtGeom& T)
{
    float pc = __expf(lv) * inv_s;   // no max-shift: logits are O(1), fp32 safe
    float cbbox = fabsf(cx - T.tx) + fabsf(cy - T.ty) + fabsf(w - T.tw) + fabsf(h - T.th);
    float iw = fminf(ax1, T.bx1) - fmaxf(ax0, T.bx0); iw = fmaxf(iw, 0.f);
    float ih = fminf(ay1, T.by1) - fmaxf(ay0, T.by0); ih = fmaxf(ih, 0.f);
    float inter = iw * ih;
    float uni = areaA + T.areaB - inter;
    float iou = __fdividef(inter, uni);
    float cw = fmaxf(ax1, T.bx1) - fminf(ax0, T.bx0);
    float ch = fmaxf(ay1, T.by1) - fminf(ay0, T.by0);
    float areaC = cw * ch;
    float giou = iou - __fdividef(areaC - uni, areaC);
    return 5.f * cbbox - pc - 2.f * giou;
}

// ---------------------------------------------------------------------------
// Single fused kernel (R9 base): one block per batch; last block -> out[0].
//  A)  single-shot TMA logits -> smem, overlapped with init/label/boxes
//  B1) thread-per-query softmax denominator FROM SMEM (validated fast path)
//  B2) flat pair cost fill + FUSED per-row argmin (reg min + 64b atomicMin)
//  D)  collision resolution  E) JV augmentation (warp 0)
//  F)  matched sum vs GLOBAL targets 0..31; PARALLEL last-block reduce
// ---------------------------------------------------------------------------
__global__ __launch_bounds__(NTHR, 1)
void fused_kernel(const float* __restrict__ logits,
                  const float* __restrict__ boxes,
                  const int*   __restrict__ lab32,
                  const float* __restrict__ tboxes,
                  float* __restrict__ out) {
    extern __shared__ float lsh[];    // [Qn*Cc] logits for this batch
    __shared__ float csh[Tt * CSTRIDE];
    __shared__ TgtGeom tloc[Tt];      // batch b's own targets (LSA block)
    __shared__ TgtGeom tg0[Tt];       // GLOBAL targets 0..31 (final sum)
    __shared__ float qinv[Qn];
    __shared__ float4 qbox[Qn];
    __shared__ unsigned long long rmin[Tt];   // fused row-argmin (key<<32 | q)
    __shared__ float u_sh[Tt + 1];
    __shared__ int   p_sh[Qn + 1];
    __shared__ float wred[NWARP];
    __shared__ int   s_flag;
    __shared__ __align__(8) unsigned long long mbar;

    const int b = blockIdx.x;
    const int tid = threadIdx.x;
    const int lane = tid & 31;
    const int wid = tid >> 5;
    const unsigned FULL = 0xffffffffu;

    // ---- A0: init mbarrier, kick off async bulk copy of logits ----
    const unsigned mbar_a = smem_u32(&mbar);
    if (tid == 0) {
        asm volatile("mbarrier.init.shared.b64 [%0], 1;" :: "r"(mbar_a) : "memory");
        s_flag = 0;
    }
    __syncthreads();
    if (tid == 0) {
        const unsigned dst = smem_u32(lsh);
        const float* src = logits + (size_t)b * Qn * Cc;
        asm volatile("mbarrier.arrive.expect_tx.shared.b64 _, [%0], %1;"
                     :: "r"(mbar_a), "r"((unsigned)LSH_BYTES) : "memory");
        asm volatile("cp.async.bulk.shared::cta.global.mbarrier::complete_tx::bytes "
                     "[%0], [%1], %2, [%3];"
                     :: "r"(dst), "l"(src), "r"((unsigned)LSH_BYTES), "r"(mbar_a)
                     : "memory");
    }

    // ---- A1 (overlapped with copy): label detect, p/rmin init, boxes ----
    for (int k = tid; k <= Qn; k += NTHR) p_sh[k] = 0;
    for (int q = tid; q < Qn; q += NTHR)
        qbox[q] = *(const float4*)(boxes + ((size_t)b * Qn + q) * 4);
    if (tid < Tt) rmin[tid] = 0xFFFFFFFFFFFFFFFFull;
    int any = 0;
    for (int k = 1 + 2 * tid; k < Nb * Tt; k += 2 * NTHR)
        if (lab32[k] != 0) any = 1;
    if (__syncthreads_or(any)) { if (tid == 0) s_flag = 1; }
    __syncthreads();
    const int is64 = (s_flag == 0);

    // ---- target geometry into shared (local + global sets) ----
    if (tid < 2 * Tt) {
        int t = tid & (Tt - 1);
        int gt = (tid < Tt) ? (b * Tt + t) : t;
        TgtGeom T;
        const float* tb = tboxes + (size_t)gt * 4;
        T.tx = tb[0]; T.ty = tb[1]; T.tw = tb[2]; T.th = tb[3];
        T.bx0 = T.tx - 0.5f * T.tw; T.by0 = T.ty - 0.5f * T.th;
        T.bx1 = T.tx + 0.5f * T.tw; T.by1 = T.ty + 0.5f * T.th;
        T.areaB = (T.bx1 - T.bx0) * (T.by1 - T.by0);
        T.lab = is64 ? lab32[2 * gt] : lab32[gt];
        if (tid < Tt) tloc[t] = T; else tg0[t] = T;
    }

    // ---- wait for logits copy completion (phase parity 0) ----
    asm volatile(
        "{\n\t.reg .pred P;\n\t"
        "W0:\n\t"
        "mbarrier.try_wait.parity.shared.b64 P, [%0], 0;\n\t"
        "@!P bra W0;\n\t}"
        :: "r"(mbar_a) : "memory");
    __syncthreads();

    // ---- B1: thread-per-query softmax denominator (pure throughput) ----
    for (int q = tid; q < Qn; q += NTHR) {
        const float* l = lsh + q * Cc;
        float s0 = 0.f, s1 = 0.f, s2 = 0.f, s3 = 0.f;
        #pragma unroll
        for (int c = 0; c < 92; c += 4) {
            s0 += __expf(l[c]);
            s1 += __expf(l[c + 1]);
            s2 += __expf(l[c + 2]);
            s3 += __expf(l[c + 3]);
        }
        qinv[q] = __fdividef(1.f, (s0 + s1) + (s2 + s3));
    }
    __syncthreads();

    // ---- B2: pair costs + fused per-row argmin (reg min, 1 atomic/thread) ----
    {
        const int t = tid & 31;
        const TgtGeom T = tloc[t];
        unsigned long long myMin = 0xFFFFFFFFFFFFFFFFull;
        for (int q = tid >> 5; q < Qn; q += NTHR / 32) {
            float4 bx = qbox[q];
            float cx = bx.x, cy = bx.y, w = bx.z, h = bx.w;
            float ax0 = cx - 0.5f * w, ay0 = cy - 0.5f * h;
            float ax1 = cx + 0.5f * w, ay1 = cy + 0.5f * h;
            float areaA = (ax1 - ax0) * (ay1 - ay0);
            float lv = lsh[q * Cc + T.lab];
            float c = pair_cost_fast(cx, cy, w, h, ax0, ay0, ax1, ay1, areaA,
                                     lv, qinv[q], T);
            csh[t * CSTRIDE + q] = c;
            unsigned long long key = ((unsigned long long)okey(c) << 32) | (unsigned)q;
            myMin = (key < myMin) ? key : myMin;
        }
        atomicMin(&rmin[t], myMin);
    }
    __syncthreads();

    // ---- D + E: warp 0 resolves collisions, augments leftovers ----
    if (wid == 0) {
        unsigned long long rm = rmin[lane];
        u_sh[lane + 1] = unkey((unsigned)(rm >> 32));   // greedy dual = rowmin
        int candv = (int)(rm & 0xFFFFFFFFu) + 1;
        __syncwarp();
        unsigned grp = __match_any_sync(FULL, candv);
        int leader = __ffs(grp) - 1;
        if (lane == leader) p_sh[candv] = lane + 1;
        unsigned un = __ballot_sync(FULL, lane != leader);
        __syncwarp();

        float v[KMAX], minv[KMAX], dacc[KMAX], uofp[KMAX];
        int   way[KMAX], prow[KMAX];
        #pragma unroll
        for (int k = 0; k < KMAX; k++) v[k] = 0.f;

        while (un) {
            int trow = __ffs(un) - 1; un &= un - 1;
            const int i = trow + 1;

            if (lane == 0) p_sh[0] = i;   // anchor for augmenting walk
            unsigned umask = 0;
            float dsum = 0.f;
            #pragma unroll
            for (int k = 0; k < KMAX; k++) {
                int q = 32 * k + lane;
                if (q < Qn) {
                    minv[k] = INF; dacc[k] = 0.f; way[k] = 0;
                    int r = p_sh[q + 1];
                    prow[k] = r;
                    uofp[k] = (r > 0) ? u_sh[r] : 0.f;
                }
            }
            __syncwarp();

            int j0 = 0, i0 = i;
            float u_i0 = u_sh[i];

            while (true) {
                if (j0 > 0 && ((j0 - 1) & 31) == lane)
                    umask |= 1u << ((j0 - 1) >> 5);

                float lmin = INF, luofp = 0.f;
                int lcol = 0, lprow = 0;
                const float* crow = &csh[(i0 - 1) * CSTRIDE];
                #pragma unroll
                for (int k = 0; k < KMAX; k++) {
                    int q = 32 * k + lane;
                    if (q < Qn && !((umask >> k) & 1u)) {
                        float cur = crow[q] - u_i0 - v[k];
                        if (cur < minv[k]) { minv[k] = cur; way[k] = j0; }
                        if (minv[k] < lmin) {
                            lmin = minv[k]; lcol = q + 1;
                            lprow = prow[k]; luofp = uofp[k];
                        }
                    }
                }

                unsigned key = okey(lmin);
                unsigned kmin = __reduce_min_sync(FULL, key);
                float delta = unkey(kmin);
                unsigned bal = __ballot_sync(FULL, key == kmin);
                int src = __ffs(bal) - 1;
                int   j1  = __shfl_sync(FULL, lcol, src);
                int   pj1 = __shfl_sync(FULL, lprow, src);
                float unx = __shfl_sync(FULL, luofp, src);

                dsum += delta;
                #pragma unroll
                for (int k = 0; k < KMAX; k++) {
                    int q = 32 * k + lane;
                    if (q < Qn) {
                        if ((umask >> k) & 1u) { v[k] -= delta; dacc[k] += delta; }
                        else                    minv[k] -= delta;
                    }
                }

                j0 = j1; i0 = pj1; u_i0 = unx;
                if (pj1 == 0) break;
            }

            #pragma unroll
            for (int k = 0; k < KMAX; k++) {
                int q = 32 * k + lane;
                if (q < Qn && ((umask >> k) & 1u) && prow[k] > 0)
                    u_sh[prow[k]] += dacc[k];
            }
            if (lane == 0) u_sh[i] += dsum;
            __syncwarp();

            int cur = j0;
            while (cur) {
                int candw = 0;
                #pragma unroll
                for (int k = 0; k < KMAX; k++)
                    if (32 * k + lane + 1 == cur) candw = way[k];
                int owner = (cur - 1) & 31;
                int wj = __shfl_sync(FULL, candw, owner);
                if (lane == 0) p_sh[cur] = p_sh[wj];
                cur = wj;
            }
            __syncwarp();
        }
    }
    __syncthreads();

    // ---- F: matched sum vs GLOBAL targets 0..31 ----
    float acc = 0.f;
    for (int j = tid + 1; j <= Qn; j += NTHR) {
        int r = p_sh[j];
        if (r > 0) {
            int q = j - 1;
            float4 bx = qbox[q];
            float cx = bx.x, cy = bx.y, w = bx.z, h = bx.w;
            float ax0 = cx - 0.5f * w, ay0 = cy - 0.5f * h;
            float ax1 = cx + 0.5f * w, ay1 = cy + 0.5f * h;
            float areaA = (ax1 - ax0) * (ay1 - ay0);
            const TgtGeom T = tg0[r - 1];
            float lv = lsh[q * Cc + T.lab];
            acc += pair_cost_fast(cx, cy, w, h, ax0, ay0, ax1, ay1, areaA,
                                  lv, qinv[q], T);
        }
    }
    #pragma unroll
    for (int off = 16; off > 0; off >>= 1)
        acc += __shfl_xor_sync(FULL, acc, off);
    if (lane == 0) wred[wid] = acc;
    __syncthreads();

    // ---- tail: block sum, then parallel last-block reduce (warp 0) ----
    if (wid == 0) {
        int isLast = 0;
        if (lane == 0) {
            float tot = 0.f;
            #pragma unroll
            for (int k = 0; k < NWARP; k++) tot += wred[k];
            g_bsum[b] = tot;
            __threadfence();
            isLast = (atomicAdd(&g_done, 1u) == Nb - 1);
        }
        isLast = __shfl_sync(FULL, isLast, 0);
        if (isLast) {
            __threadfence();                       // acquire all g_bsum writes
            float s = g_bsum[lane];                // 32 concurrent loads
            #pragma unroll
            for (int off = 16; off > 0; off >>= 1)
                s += __shfl_xor_sync(FULL, s, off);  // fixed-order tree: deterministic
            if (lane == 0) {
                out[0] = s;
                atomicExch(&g_done, 0u);           // reset for next replay
            }
        }
    }
}

extern "C" void kernel_launch(void* const* d_in, const int* in_sizes, int n_in,
                              void* d_out, int out_size) {
    const float* pred_logits = (const float*)d_in[0];
    const float* pred_boxes  = (const float*)d_in[1];
    const int*   tgt_lab32   = (const int*)d_in[2];   // int32 view; layout auto-detected
    const float* tgt_boxes   = (const float*)d_in[3];
    float* out = (float*)d_out;

    cudaFuncSetAttribute(fused_kernel,
                         cudaFuncAttributeMaxDynamicSharedMemorySize, LSH_BYTES);
    fused_kernel<<<Nb, NTHR, LSH_BYTES>>>(pred_logits, pred_boxes, tgt_lab32,
                                          tgt_boxes, out);
}

// round 14
// speedup vs baseline: 1.3401x; 1.1083x over previous
#include <cuda_runtime.h>

#define Nb 32
#define Qn 300
#define Cc 92
#define Tt 32
#define NTHR 512
#define NWARP (NTHR/32)
#define INF 1e30f
#define CSTRIDE 301   // padded smem row stride
#define KMAX 10       // ceil(300/32) columns per lane (warp-0 solver)
#define LSH_BYTES (Qn * Cc * 4)   // 110,400 B dynamic smem for logits
#define NCH 10
#define CHB (LSH_BYTES / NCH)     // 11,040 B per chunk (multiple of 16)

__device__ float    g_bsum[Nb];
__device__ unsigned g_done = 0;

// order-preserving float<->uint keys for __reduce_min_sync
__device__ __forceinline__ unsigned okey(float f) {
    unsigned bb = __float_as_uint(f);
    return bb ^ (unsigned)(((int)bb >> 31) | 0x80000000);
}
__device__ __forceinline__ float unkey(unsigned k) {
    unsigned bb = (k & 0x80000000u) ? (k ^ 0x80000000u) : ~k;
    return __uint_as_float(bb);
}

__device__ __forceinline__ unsigned smem_u32(const void* p) {
    unsigned a;
    asm("{ .reg .u64 t; cvta.to.shared.u64 t, %1; cvt.u32.u64 %0, t; }"
        : "=r"(a) : "l"(p));
    return a;
}

struct TgtGeom {            // precomputed per-target geometry
    float tx, ty, tw, th;   // raw cxcywh
    float bx0, by0, bx1, by1, areaB;
    int   lab;
};

__device__ __forceinline__ float pair_cost_fast(
    float cx, float cy, float w, float h,
    float ax0, float ay0, float ax1, float ay1, float areaA,
    float lv, float inv_s, const TgtGeom& T)
{
    float pc = __expf(lv) * inv_s;   // no max-shift: logits are O(1), fp32 safe
    float cbbox = fabsf(cx - T.tx) + fabsf(cy - T.ty) + fabsf(w - T.tw) + fabsf(h - T.th);
    float iw = fminf(ax1, T.bx1) - fmaxf(ax0, T.bx0); iw = fmaxf(iw, 0.f);
    float ih = fminf(ay1, T.by1) - fmaxf(ay0, T.by0); ih = fmaxf(ih, 0.f);
    float inter = iw * ih;
    float uni = areaA + T.areaB - inter;
    float iou = __fdividef(inter, uni);
    float cw = fmaxf(ax1, T.bx1) - fminf(ax0, T.bx0);
    float ch = fmaxf(ay1, T.by1) - fminf(ay0, T.by0);
    float areaC = cw * ch;
    float giou = iou - __fdividef(areaC - uni, areaC);
    return 5.f * cbbox - pc - 2.f * giou;
}

// ---------------------------------------------------------------------------
// Single fused kernel (R9 base): one block per batch; last block -> out[0].
//  A)  logits -> smem via 10 CONCURRENT TMA chunks, ONE mbarrier, ONE wait
//  B1) thread-per-query softmax denominator from smem
//  B2) flat pair loop cost fill (target geometry register-resident)
//  C) per-row argmin  D) collision resolution  E) JV augmentation (warp 0)
//  F) matched sum vs GLOBAL targets 0..31; last-block final reduce
// ---------------------------------------------------------------------------
__global__ __launch_bounds__(NTHR, 1)
void fused_kernel(const float* __restrict__ logits,
                  const float* __restrict__ boxes,
                  const int*   __restrict__ lab32,
                  const float* __restrict__ tboxes,
                  float* __restrict__ out) {
    extern __shared__ float lsh[];    // [Qn*Cc] logits for this batch
    __shared__ float csh[Tt * CSTRIDE];
    __shared__ TgtGeom tloc[Tt];      // batch b's own targets (LSA block)
    __shared__ TgtGeom tg0[Tt];       // GLOBAL targets 0..31 (final sum)
    __shared__ float qinv[Qn];
    __shared__ float4 qbox[Qn];
    __shared__ float u_sh[Tt + 1];
    __shared__ int   p_sh[Qn + 1];
    __shared__ int   cand[Tt];
    __shared__ float wred[NWARP];
    __shared__ int   s_flag;
    __shared__ __align__(8) unsigned long long mbar;

    const int b = blockIdx.x;
    const int tid = threadIdx.x;
    const int lane = tid & 31;
    const int wid = tid >> 5;
    const unsigned FULL = 0xffffffffu;

    // ---- A0: init mbarrier, kick off 10 concurrent bulk copies ----
    const unsigned mbar_a = smem_u32(&mbar);
    if (tid == 0) {
        asm volatile("mbarrier.init.shared.b64 [%0], 1;" :: "r"(mbar_a) : "memory");
        s_flag = 0;
    }
    __syncthreads();
    if (tid == 0) {
        const unsigned dst0 = smem_u32(lsh);
        const char* src0 = (const char*)(logits + (size_t)b * Qn * Cc);
        asm volatile("mbarrier.arrive.expect_tx.shared.b64 _, [%0], %1;"
                     :: "r"(mbar_a), "r"((unsigned)LSH_BYTES) : "memory");
        #pragma unroll
        for (int c = 0; c < NCH; c++) {
            asm volatile("cp.async.bulk.shared::cta.global.mbarrier::complete_tx::bytes "
                         "[%0], [%1], %2, [%3];"
                         :: "r"(dst0 + c * CHB), "l"(src0 + (size_t)c * CHB),
                            "r"((unsigned)CHB), "r"(mbar_a) : "memory");
        }
    }

    // ---- A1 (overlapped with copies): label detect, p init, boxes ----
    for (int k = tid; k <= Qn; k += NTHR) p_sh[k] = 0;
    for (int q = tid; q < Qn; q += NTHR)
        qbox[q] = *(const float4*)(boxes + ((size_t)b * Qn + q) * 4);
    int any = 0;
    for (int k = 1 + 2 * tid; k < Nb * Tt; k += 2 * NTHR)
        if (lab32[k] != 0) any = 1;
    if (__syncthreads_or(any)) { if (tid == 0) s_flag = 1; }
    __syncthreads();
    const int is64 = (s_flag == 0);

    // ---- target geometry into shared (local + global sets) ----
    if (tid < 2 * Tt) {
        int t = tid & (Tt - 1);
        int gt = (tid < Tt) ? (b * Tt + t) : t;
        TgtGeom T;
        const float* tb = tboxes + (size_t)gt * 4;
        T.tx = tb[0]; T.ty = tb[1]; T.tw = tb[2]; T.th = tb[3];
        T.bx0 = T.tx - 0.5f * T.tw; T.by0 = T.ty - 0.5f * T.th;
        T.bx1 = T.tx + 0.5f * T.tw; T.by1 = T.ty + 0.5f * T.th;
        T.areaB = (T.bx1 - T.bx0) * (T.by1 - T.by0);
        T.lab = is64 ? lab32[2 * gt] : lab32[gt];
        if (tid < Tt) tloc[t] = T; else tg0[t] = T;
    }

    // ---- wait for ALL chunk copies (one barrier, phase parity 0) ----
    asm volatile(
        "{\n\t.reg .pred P;\n\t"
        "W0:\n\t"
        "mbarrier.try_wait.parity.shared.b64 P, [%0], 0;\n\t"
        "@!P bra W0;\n\t}"
        :: "r"(mbar_a) : "memory");
    __syncthreads();

    // ---- B1: thread-per-query softmax denominator (pure throughput) ----
    for (int q = tid; q < Qn; q += NTHR) {
        const float* l = lsh + q * Cc;
        float s0 = 0.f, s1 = 0.f, s2 = 0.f, s3 = 0.f;
        #pragma unroll
        for (int c = 0; c < 92; c += 4) {
            s0 += __expf(l[c]);
            s1 += __expf(l[c + 1]);
            s2 += __expf(l[c + 2]);
            s3 += __expf(l[c + 3]);
        }
        qinv[q] = __fdividef(1.f, (s0 + s1) + (s2 + s3));
    }
    __syncthreads();

    // ---- B2: flat pair loop; t fixed per thread -> geometry in registers ----
    {
        const int t = tid & 31;
        const TgtGeom T = tloc[t];
        for (int q = tid >> 5; q < Qn; q += NTHR / 32) {
            float4 bx = qbox[q];
            float cx = bx.x, cy = bx.y, w = bx.z, h = bx.w;
            float ax0 = cx - 0.5f * w, ay0 = cy - 0.5f * h;
            float ax1 = cx + 0.5f * w, ay1 = cy + 0.5f * h;
            float areaA = (ax1 - ax0) * (ay1 - ay0);
            float lv = lsh[q * Cc + T.lab];
            csh[t * CSTRIDE + q] =
                pair_cost_fast(cx, cy, w, h, ax0, ay0, ax1, ay1, areaA,
                               lv, qinv[q], T);
        }
    }
    __syncthreads();

    // ---- C: per-row argmin (greedy duals u[t] = rowmin, v = 0) ----
    for (int t = wid; t < Tt; t += NWARP) {
        float lmin = INF; int lq = 0;
        #pragma unroll
        for (int k = 0; k < KMAX; k++) {
            int q = 32 * k + lane;
            if (q < Qn) {
                float c = csh[t * CSTRIDE + q];
                if (c < lmin) { lmin = c; lq = q; }
            }
        }
        unsigned key = okey(lmin);
        unsigned kmin = __reduce_min_sync(FULL, key);
        unsigned bal = __ballot_sync(FULL, key == kmin);
        int src = __ffs(bal) - 1;
        int bq = __shfl_sync(FULL, lq, src);
        if (lane == 0) { u_sh[t + 1] = unkey(kmin); cand[t] = bq + 1; }
    }
    __syncthreads();

    // ---- D + E: warp 0 resolves collisions, augments leftovers ----
    if (wid == 0) {
        int candv = cand[lane];
        unsigned grp = __match_any_sync(FULL, candv);
        int leader = __ffs(grp) - 1;
        if (lane == leader) p_sh[candv] = lane + 1;
        unsigned un = __ballot_sync(FULL, lane != leader);
        __syncwarp();

        float v[KMAX], minv[KMAX], dacc[KMAX], uofp[KMAX];
        int   way[KMAX], prow[KMAX];
        #pragma unroll
        for (int k = 0; k < KMAX; k++) v[k] = 0.f;

        while (un) {
            int trow = __ffs(un) - 1; un &= un - 1;
            const int i = trow + 1;

            if (lane == 0) p_sh[0] = i;   // anchor for augmenting walk
            unsigned umask = 0;
            float dsum = 0.f;
            #pragma unroll
            for (int k = 0; k < KMAX; k++) {
                int q = 32 * k + lane;
                if (q < Qn) {
                    minv[k] = INF; dacc[k] = 0.f; way[k] = 0;
                    int r = p_sh[q + 1];
                    prow[k] = r;
                    uofp[k] = (r > 0) ? u_sh[r] : 0.f;
                }
            }
            __syncwarp();

            int j0 = 0, i0 = i;
            float u_i0 = u_sh[i];

            while (true) {
                if (j0 > 0 && ((j0 - 1) & 31) == lane)
                    umask |= 1u << ((j0 - 1) >> 5);

                float lmin = INF, luofp = 0.f;
                int lcol = 0, lprow = 0;
                const float* crow = &csh[(i0 - 1) * CSTRIDE];
                #pragma unroll
                for (int k = 0; k < KMAX; k++) {
                    int q = 32 * k + lane;
                    if (q < Qn && !((umask >> k) & 1u)) {
                        float cur = crow[q] - u_i0 - v[k];
                        if (cur < minv[k]) { minv[k] = cur; way[k] = j0; }
                        if (minv[k] < lmin) {
                            lmin = minv[k]; lcol = q + 1;
                            lprow = prow[k]; luofp = uofp[k];
                        }
                    }
                }

                unsigned key = okey(lmin);
                unsigned kmin = __reduce_min_sync(FULL, key);
                float delta = unkey(kmin);
                unsigned bal = __ballot_sync(FULL, key == kmin);
                int src = __ffs(bal) - 1;
                int   j1  = __shfl_sync(FULL, lcol, src);
                int   pj1 = __shfl_sync(FULL, lprow, src);
                float unx = __shfl_sync(FULL, luofp, src);

                dsum += delta;
                #pragma unroll
                for (int k = 0; k < KMAX; k++) {
                    int q = 32 * k + lane;
                    if (q < Qn) {
                        if ((umask >> k) & 1u) { v[k] -= delta; dacc[k] += delta; }
                        else                    minv[k] -= delta;
                    }
                }

                j0 = j1; i0 = pj1; u_i0 = unx;
                if (pj1 == 0) break;
            }

            #pragma unroll
            for (int k = 0; k < KMAX; k++) {
                int q = 32 * k + lane;
                if (q < Qn && ((umask >> k) & 1u) && prow[k] > 0)
                    u_sh[prow[k]] += dacc[k];
            }
            if (lane == 0) u_sh[i] += dsum;
            __syncwarp();

            int cur = j0;
            while (cur) {
                int candw = 0;
                #pragma unroll
                for (int k = 0; k < KMAX; k++)
                    if (32 * k + lane + 1 == cur) candw = way[k];
                int owner = (cur - 1) & 31;
                int wj = __shfl_sync(FULL, candw, owner);
                if (lane == 0) p_sh[cur] = p_sh[wj];
                cur = wj;
            }
            __syncwarp();
        }
    }
    __syncthreads();

    // ---- F: matched sum vs GLOBAL targets 0..31 ----
    float acc = 0.f;
    for (int j = tid + 1; j <= Qn; j += NTHR) {
        int r = p_sh[j];
        if (r > 0) {
            int q = j - 1;
            float4 bx = qbox[q];
            float cx = bx.x, cy = bx.y, w = bx.z, h = bx.w;
            float ax0 = cx - 0.5f * w, ay0 = cy - 0.5f * h;
            float ax1 = cx + 0.5f * w, ay1 = cy + 0.5f * h;
            float areaA = (ax1 - ax0) * (ay1 - ay0);
            const TgtGeom T = tg0[r - 1];
            float lv = lsh[q * Cc + T.lab];
            acc += pair_cost_fast(cx, cy, w, h, ax0, ay0, ax1, ay1, areaA,
                                  lv, qinv[q], T);
        }
    }
    #pragma unroll
    for (int off = 16; off > 0; off >>= 1)
        acc += __shfl_xor_sync(FULL, acc, off);
    if (lane == 0) wred[wid] = acc;
    __syncthreads();
    if (tid == 0) {
        float tot = 0.f;
        #pragma unroll
        for (int k = 0; k < NWARP; k++) tot += wred[k];
        g_bsum[b] = tot;
        __threadfence();
        unsigned ticket = atomicAdd(&g_done, 1u);
        if (ticket == Nb - 1) {
            float s = 0.f;
            for (int k = 0; k < Nb; k++) s += g_bsum[k];
            out[0] = s;
            atomicExch(&g_done, 0u);   // reset for next replay (deterministic)
        }
    }
}

extern "C" void kernel_launch(void* const* d_in, const int* in_sizes, int n_in,
                              void* d_out, int out_size) {
    const float* pred_logits = (const float*)d_in[0];
    const float* pred_boxes  = (const float*)d_in[1];
    const int*   tgt_lab32   = (const int*)d_in[2];   // int32 view; layout auto-detected
    const float* tgt_boxes   = (const float*)d_in[3];
    float* out = (float*)d_out;

    cudaFuncSetAttribute(fused_kernel,
                         cudaFuncAttributeMaxDynamicSharedMemorySize, LSH_BYTES);
    fused_kernel<<<Nb, NTHR, LSH_BYTES>>>(pred_logits, pred_boxes, tgt_lab32,
                                          tgt_boxes, out);
}